// round 16
// baseline (speedup 1.0000x reference)
#include <cuda_runtime.h>
#include <cuda_bf16.h>
#include <cstdint>

// Problem constants
#define BS     2
#define NM     10
#define NA     8400
#define NAP    8416    // padded per-bm span (263*32): warps never straddle a bm
#define NC     80
#define NPT    360
#define NBINS  36
#define NB2    72      // 5-degree buckets
#define NBM    (BS*NM)
#define BSNMNA (BS*NM*NA)
#define BSNA   (BS*NA)
#define MAXL   1024
#define FULLM  0xffffffffu
#define WPB    8
#define GBLK   592     // 4 blocks per SM; co-residency proven in R15
#define NWARP  (GBLK*WPB)
#define NTHR   (GBLK*256)

// Output layout (flat float32, reference tuple order)
#define TL_OFF      0
#define TB_OFF      16800
#define TS_OFF      84000
#define MPB_OFF     1428000
#define TGI_OFF     1596000
#define GTDIST_OFF  1612800
#define CENT_OFF    7660800
#define FG_OFF      7828800
#define OUT_TOTAL   7845600
#define OUT_VEC4    (OUT_TOTAL/4)

// Scratch. All control state returns to zero by replay end -> replay-invariant.
__device__ float g_align[BSNMNA];
__device__ float g_overlaps[BSNMNA];
__device__ float g_cent[BSNMNA];
__device__ __align__(16) float g_dist[(size_t)BSNMNA * NBINS];
__device__ int   g_liveA[NBM * MAXL];
__device__ int   g_cnt[NBM];
__device__ int   g_pairdone[NBM];       // self-reset by detecting block
__device__ unsigned g_inbits[BSNA];     // sparse atomicOr; re-zeroed in P3
__device__ unsigned g_topkbits[BSNA];
__device__ unsigned g_posA[NBM];
__device__ unsigned g_posO[NBM];
__device__ unsigned g_barA[4], g_barB[4];

__device__ __forceinline__ unsigned long long ullmax2(unsigned long long a, unsigned long long b){ return a>b?a:b; }

__device__ __forceinline__ void ins4(unsigned long long key,
    unsigned long long& k0, unsigned long long& k1,
    unsigned long long& k2, unsigned long long& k3)
{
    if (key < k3) {
        k3 = key;
        unsigned long long tmp;
        if (k3 < k2) { tmp=k2; k2=k3; k3=tmp; }
        if (k2 < k1) { tmp=k1; k1=k2; k2=tmp; }
        if (k1 < k0) { tmp=k0; k0=k1; k1=tmp; }
    }
}

// two-counter grid barrier; all GBLK blocks co-resident by construction
__device__ __forceinline__ void gridbar(int i) {
    __syncthreads();
    if (threadIdx.x == 0) {
        __threadfence();
        atomicAdd(&g_barA[i], 1u);
        while (*((volatile unsigned*)&g_barA[i]) < (unsigned)GBLK) { }
        __threadfence();
        unsigned o = atomicAdd(&g_barB[i], 1u);
        if (o == GBLK - 1) { atomicExch(&g_barA[i], 0u); atomicExch(&g_barB[i], 0u); }
    }
    __syncthreads();
}

struct WarpScratch {
    unsigned long long sAI[NPT];  // (ang_bits<<32)|idx, bucket-contiguous CSR
    float r2[NPT];                // squared distance, by point id
    int scnt[NB2];
    int scur[NB2];
    int pfx2[3*NB2 + 1];
};

union SmemPool {
    WarpScratch ws[WPB];
    unsigned long long s_topk[MAXL];   // used only after block-wide syncthreads
};

// ---------------------------------------------------------------------------
// The whole assigner in one persistent kernel (4 blocks/SM), inline top-13
// ---------------------------------------------------------------------------
__global__ __launch_bounds__(256, 4) void k_all(
    const float* __restrict__ pd_scores,
    const float* __restrict__ pd_bboxes,
    const float* __restrict__ anc,
    const int*   __restrict__ gt_labels,
    const float* __restrict__ gt_bboxes,
    const float* __restrict__ mask_gt,
    const float* __restrict__ gt_coor,
    float* __restrict__ out)
{
    __shared__ SmemPool sp;
    __shared__ int sFlag[WPB];
    __shared__ int sNflag;

    int tid = threadIdx.x;
    int lane = tid & 31;
    int wid = tid >> 5;
    int gt = blockIdx.x * 256 + tid;          // global thread id

    // ================= P0: zero output + compact =================
    {
        float4 z = make_float4(0.f, 0.f, 0.f, 0.f);
        float4* out4 = (float4*)out;
        for (int i = gt; i < OUT_VEC4; i += NTHR) out4[i] = z;

        if (gt < NBM) { g_posA[gt] = 0u; g_posO[gt] = 0u; }

        for (int t = gt; t < NBM * NAP; t += NTHR) {
            int bm = t / NAP;
            int a  = t - bm * NAP;
            bool live = false;
            if (a < NA && __ldg(&mask_gt[bm]) != 0.f) {
                float2 p = __ldg(&((const float2*)anc)[a]);
                float lx = __ldg(&gt_bboxes[bm*4+0]);
                float ly = __ldg(&gt_bboxes[bm*4+1]);
                float rx = __ldg(&gt_bboxes[bm*4+2]);
                float ry = __ldg(&gt_bboxes[bm*4+3]);
                float mind = fminf(fminf(p.x - lx, p.y - ly), fminf(rx - p.x, ry - p.y));
                live = (mind > 1e-9f);
            }
            unsigned set = __ballot_sync(FULLM, live);   // warp shares one bm (NAP%32==0)
            if (set) {
                int bmu = __shfl_sync(FULLM, bm, 0);
                int leader = __ffs(set) - 1;
                int base = 0;
                if (lane == leader) base = atomicAdd(&g_cnt[bmu], __popc(set));
                base = __shfl_sync(FULLM, base, leader);
                if (live) {
                    int s = base + __popc(set & ((1u << lane) - 1u));
                    if (s < MAXL) g_liveA[bm*MAXL + s] = a;
                    int bb = bm / NM, mm = bm - bb*NM;
                    atomicOr(&g_inbits[bb*NA + a], 1u << mm);
                }
            }
        }
    }
    gridbar(0);

    // ================= P1: pairs (block owns 8 contiguous pairs) + inline topk
    int pfx[NBM + 1];
    {
        pfx[0] = 0;
        #pragma unroll
        for (int i = 0; i < NBM; i++) {
            int c = g_cnt[i]; if (c > MAXL) c = MAXL;
            pfx[i+1] = pfx[i] + c;
        }
        int total = pfx[NBM];
        int p = blockIdx.x * WPB + wid;

        if (p < total) {
            int bm = 0;
            #pragma unroll
            for (int i = 1; i < NBM; i++) bm += (p >= pfx[i]);
            int j = p - pfx[bm];
            int b = bm / NM;

            WarpScratch& S = sp.ws[wid];
            const float2* gp2 = (const float2*)(gt_coor + (size_t)bm * (2*NPT));
            int label = gt_labels[bm];
            int a = g_liveA[bm*MAXL + j];
            float2 ap = ((const float2*)anc)[a];
            float ax = ap.x, ay = ap.y;
            int pairIdx = bm * NA + a;

            S.scnt[lane] = 0;
            S.scnt[32 + lane] = 0;
            if (lane < 8) S.scnt[64 + lane] = 0;
            __syncwarp();

            float angR[12];
            #pragma unroll
            for (int i = 0; i < 12; i++) {
                int pp = lane + 32*i;
                if (pp < NPT) {
                    float2 pt = gp2[pp];
                    float dx = pt.x - ax, dy = pt.y - ay;
                    S.r2[pp] = dx*dx + dy*dy;
                    float ang = atan2f(dy, dx) * 57.29577951308232f;
                    if (ang < 0.f) ang += 360.f;
                    angR[i] = ang;
                    int bk = (int)(ang * 0.2f);
                    if (bk > NB2-1) bk = NB2-1;
                    atomicAdd(&S.scnt[bk], 1);
                }
            }
            __syncwarp();

            {
                int v0 = S.scnt[lane];
                int v1 = S.scnt[32 + lane];
                int v2 = (lane < 8) ? S.scnt[64 + lane] : 0;
                int c0 = v0, c1 = v1, c2 = v2;
                #pragma unroll
                for (int off = 1; off < 32; off <<= 1) {
                    int n0 = __shfl_up_sync(FULLM, c0, off);
                    int n1 = __shfl_up_sync(FULLM, c1, off);
                    if (lane >= off) { c0 += n0; c1 += n1; }
                }
                int tot0 = __shfl_sync(FULLM, c0, 31);
                int tot01 = tot0 + __shfl_sync(FULLM, c1, 31);
                #pragma unroll
                for (int off = 1; off < 8; off <<= 1) {
                    int n2 = __shfl_up_sync(FULLM, c2, off);
                    if (lane >= off) c2 += n2;
                }
                int e0 = c0 - v0;
                int e1 = tot0 + c1 - v1;
                int e2 = tot01 + c2 - v2;
                S.scur[lane] = e0;
                S.pfx2[lane] = e0; S.pfx2[lane+NB2] = e0+NPT; S.pfx2[lane+2*NB2] = e0+2*NPT;
                int k1i = 32 + lane;
                S.scur[k1i] = e1;
                S.pfx2[k1i] = e1; S.pfx2[k1i+NB2] = e1+NPT; S.pfx2[k1i+2*NB2] = e1+2*NPT;
                if (lane < 8) {
                    int k2i = 64 + lane;
                    S.scur[k2i] = e2;
                    S.pfx2[k2i] = e2; S.pfx2[k2i+NB2] = e2+NPT; S.pfx2[k2i+2*NB2] = e2+2*NPT;
                }
                if (lane == 0) S.pfx2[3*NB2] = 3*NPT;
            }
            __syncwarp();

            #pragma unroll
            for (int i = 0; i < 12; i++) {
                int pp = lane + 32*i;
                if (pp < NPT) {
                    int bk = (int)(angR[i] * 0.2f);
                    if (bk > NB2-1) bk = NB2-1;
                    int pos = atomicAdd(&S.scur[bk], 1);
                    S.sAI[pos] = ((unsigned long long)__float_as_uint(angR[i]) << 32) | (unsigned)pp;
                }
            }
            __syncwarp();

            // bin phase: lane-owned bins, minimal count>=4 ring at 5-deg buckets
            float dmv0 = 1e-6f, dmv1 = 1e-6f;
            #pragma unroll
            for (int pass = 0; pass < 2; pass++) {
                int bin = lane + 32*pass;
                if (pass == 1 && lane >= 4) break;
                int i0 = 2*bin;
                float dmv;
                int c0cnt = S.pfx2[i0+73] - S.pfx2[i0+71];
                if (c0cnt == 0) {
                    dmv = 1e-6f;
                } else {
                    int L = 0, lo, hi;
                    for (;; L++) {
                        lo = S.pfx2[i0+71-L];
                        hi = S.pfx2[i0+73+L];
                        if (hi - lo >= 4) break;
                    }
                    int W, pos, n1;
                    if (2*L + 2 >= NB2) { pos = 0; W = NPT; n1 = NPT; }
                    else {
                        W = hi - lo;
                        pos = lo; while (pos >= NPT) pos -= NPT;
                        n1 = NPT - pos; if (n1 > W) n1 = W;
                    }
                    float th = (float)(bin * 10);
                    unsigned long long k0=~0ull,k1=~0ull,k2=~0ull,k3=~0ull;
                    for (int c = 0; c < n1; c++) {
                        unsigned long long ai = S.sAI[pos + c];
                        float ang = __uint_as_float((unsigned)(ai >> 32));
                        float df = fabsf(ang - th);
                        if (df > 180.f) df = 360.f - df;
                        ins4(((unsigned long long)__float_as_uint(df) << 32) |
                             (unsigned)(ai & 0xffffffffu), k0, k1, k2, k3);
                    }
                    for (int c = 0; c < W - n1; c++) {
                        unsigned long long ai = S.sAI[c];
                        float ang = __uint_as_float((unsigned)(ai >> 32));
                        float df = fabsf(ang - th);
                        if (df > 180.f) df = 360.f - df;
                        ins4(((unsigned long long)__float_as_uint(df) << 32) |
                             (unsigned)(ai & 0xffffffffu), k0, k1, k2, k3);
                    }
                    float mindiff = __uint_as_float((unsigned)(k0 >> 32));
                    if (mindiff > 3.0f) {
                        dmv = 1e-6f;
                    } else {
                        float mr2 = S.r2[(unsigned)(k0 & 0xffffffffu)];
                        mr2 = fmaxf(mr2, S.r2[(unsigned)(k1 & 0xffffffffu)]);
                        mr2 = fmaxf(mr2, S.r2[(unsigned)(k2 & 0xffffffffu)]);
                        mr2 = fmaxf(mr2, S.r2[(unsigned)(k3 & 0xffffffffu)]);
                        dmv = fmaxf(sqrtf(mr2), 1e-6f);
                    }
                }
                if (pass == 0) dmv0 = dmv; else dmv1 = dmv;
            }

            // g_dist write (lane-owned bins)
            {
                float* gd = g_dist + (size_t)pairIdx * NBINS;
                gd[lane] = dmv0;
                if (lane < 4) gd[32 + lane] = dmv1;
            }

            // epilogue: iou + centerness + align (lane-owned dm values; R12-proven)
            {
                const float* pb = pd_bboxes + ((size_t)b*NA + a) * NBINS;
                float p0v = pb[lane];
                float smin = fmaxf(fminf(dmv0, p0v), 1e-6f);
                float smax = fmaxf(dmv0, p0v);
                float mn = dmv0, mx = dmv0;
                if (lane < 4) {
                    float p1v = pb[32 + lane];
                    smin += fmaxf(fminf(dmv1, p1v), 1e-6f);
                    smax += fmaxf(dmv1, p1v);
                    mn = fminf(mn, dmv1);
                    mx = fmaxf(mx, dmv1);
                }
                #pragma unroll
                for (int off = 16; off; off >>= 1) {
                    smin += __shfl_xor_sync(FULLM, smin, off);
                    smax += __shfl_xor_sync(FULLM, smax, off);
                    mn = fminf(mn, __shfl_xor_sync(FULLM, mn, off));
                    mx = fmaxf(mx, __shfl_xor_sync(FULLM, mx, off));
                }
                if (lane == 0) {
                    float iou = smin / smax;
                    float score = pd_scores[((size_t)b*NA + a) * NC + label];
                    g_overlaps[pairIdx] = iou;
                    g_align[pairIdx]    = score * iou * iou * iou;
                    g_cent[pairIdx]     = sqrtf(mn / mx);
                }
            }
        }

        // ---- per-bm completion counting + inline top-13 (R13 pattern) ----
        __syncthreads();           // retires all ws usage; pairs of block done
        if (tid == 0) {
            sNflag = 0;
            int p0b = blockIdx.x * WPB;
            int p1b = p0b + WPB; if (p1b > total) p1b = total;
            if (p1b > p0b) {
                __threadfence();   // release this block's g_align writes
                int pp = p0b;
                while (pp < p1b) {
                    int bm = 0;
                    #pragma unroll
                    for (int i = 1; i < NBM; i++) bm += (pp >= pfx[i]);
                    int end = pfx[bm+1]; if (end > p1b) end = p1b;
                    int n = end - pp;
                    int cntbm = pfx[bm+1] - pfx[bm];
                    int old = atomicAdd(&g_pairdone[bm], n);
                    if (old + n == cntbm) {
                        g_pairdone[bm] = 0;          // all arrived; reset for replay
                        sFlag[sNflag++] = bm;
                    }
                    pp = end;
                }
            }
        }
        __syncthreads();
        if (wid == 0 && sNflag > 0) {
            __threadfence();       // acquire other blocks' g_align writes
            for (int f = 0; f < sNflag; f++) {
                int bm = sFlag[f];
                int cnt = pfx[bm+1] - pfx[bm];
                const int* la = g_liveA + bm*MAXL;
                for (int jj = lane; jj < cnt; jj += 32) {
                    int a = la[jj];
                    float v = g_align[bm*NA + a];
                    sp.s_topk[jj] = ((unsigned long long)__float_as_uint(v) << 32) | (unsigned)(NA - a);
                }
                __syncwarp();
                int b = bm / NM, m = bm % NM;
                int kmax = cnt < 13 ? cnt : 13;
                for (int k = 0; k < kmax; k++) {
                    unsigned long long best = 0;
                    for (int jj = lane; jj < cnt; jj += 32) best = ullmax2(best, sp.s_topk[jj]);
                    #pragma unroll
                    for (int off = 16; off; off >>= 1)
                        best = ullmax2(best, __shfl_xor_sync(FULLM, best, off));
                    if (best == 0) break;
                    for (int jj = lane; jj < cnt; jj += 32) if (sp.s_topk[jj] == best) sp.s_topk[jj] = 0;
                    if (lane == 0) {
                        int a = NA - (int)(best & 0xffffffffu);
                        atomicOr(&g_topkbits[b*NA + a], 1u << m);
                    }
                    __syncwarp();
                }
            }
        }
    }
    gridbar(1);

    // ================= P3: per-anchor resolution + outputs =================
    unsigned fin = 0;
    int b_ = 0, a_ = 0;
    {
        int t = gt;
        if (t < BSNA) {
            b_ = t / NA; a_ = t % NA;
            unsigned tb  = g_topkbits[t];
            unsigned inb = g_inbits[t];
            g_topkbits[t] = 0u;
            g_inbits[t]   = 0u;
            fin = tb;
            if (__popc(tb) > 1) {
                float best = -1.f; int bi = 0;
                #pragma unroll
                for (int m = 0; m < NM; m++) {
                    float o = ((inb >> m) & 1u) ? g_overlaps[(b_*NM+m)*NA + a_] : 0.f;
                    if (o > best) { best = o; bi = m; }
                }
                fin = 1u << bi;
            }

            int tgt = fin ? (__ffs(fin) - 1) : 0;
            out[FG_OFF + t]  = fin ? 1.f : 0.f;
            out[TGI_OFF + t] = (float)tgt;
            int lbl = gt_labels[b_*NM + tgt]; if (lbl < 0) lbl = 0;
            out[TL_OFF + t] = (float)lbl;
            const float4* gb4 = (const float4*)(gt_bboxes);
            ((float4*)(out + TB_OFF))[t] = gb4[b_*NM + tgt];

            if (fin) {
                int idx = (b_*NM + tgt)*NA + a_;
                out[MPB_OFF + idx]  = 1.f;
                out[CENT_OFF + idx] = g_cent[idx];
                atomicMax(&g_posA[b_*NM + tgt], __float_as_uint(g_align[idx]));
                atomicMax(&g_posO[b_*NM + tgt], __float_as_uint(g_overlaps[idx]));
                const float4* src = (const float4*)(g_dist + (size_t)idx * NBINS);
                float4* dst = (float4*)(out + GTDIST_OFF + (size_t)idx * NBINS);
                #pragma unroll
                for (int e = 0; e < NBINS/4; e++) dst[e] = src[e];
            }
        }
        if (t < NBM) g_cnt[t] = 0;     // reset for next replay (topk done)
    }
    gridbar(2);

    // ================= P4: target_scores for positives =====================
    if (gt < BSNA && fin) {
        int m = __ffs(fin) - 1;
        int bm = b_*NM + m;
        float A = __uint_as_float(g_posA[bm]);
        float O = __uint_as_float(g_posO[bm]);
        float norm = g_align[bm*NA + a_] * O / (A + 1e-9f);
        int lbl = gt_labels[bm]; if (lbl < 0) lbl = 0;
        out[TS_OFF + (size_t)gt * NC + lbl] = norm;
    }
}

// ---------------------------------------------------------------------------
extern "C" void kernel_launch(void* const* d_in, const int* in_sizes, int n_in,
                              void* d_out, int out_size) {
    const float* pd_scores = (const float*)d_in[0];
    const float* pd_bboxes = (const float*)d_in[1];
    const float* anc       = (const float*)d_in[2];
    const int*   gt_labels = (const int*)  d_in[3];
    const float* gt_bboxes = (const float*)d_in[4];
    const float* mask_gt   = (const float*)d_in[5];
    const float* gt_coor   = (const float*)d_in[6];
    float* out = (float*)d_out;

    k_all<<<GBLK, 256>>>(pd_scores, pd_bboxes, anc, gt_labels, gt_bboxes,
                         mask_gt, gt_coor, out);
}

// round 17
// speedup vs baseline: 1.1626x; 1.1626x over previous
#include <cuda_runtime.h>
#include <cuda_bf16.h>
#include <cstdint>

// Problem constants
#define BS     2
#define NM     10
#define NA     8400
#define NAP    8416    // padded per-bm span (263*32): warps never straddle a bm
#define NC     80
#define NPT    360
#define NBINS  36
#define NB2    72      // 5-degree buckets
#define NBM    (BS*NM)
#define BSNMNA (BS*NM*NA)
#define BSNA   (BS*NA)
#define MAXL   1024
#define FULLM  0xffffffffu
#define WPB    8
#define ABLK   66      // blocks in fused assign kernel (66*256 >= 16800)

// Output layout (flat float32, reference tuple order)
#define TL_OFF      0
#define TB_OFF      16800
#define TS_OFF      84000
#define MPB_OFF     1428000
#define TGI_OFF     1596000
#define GTDIST_OFF  1612800
#define CENT_OFF    7660800
#define FG_OFF      7828800
#define OUT_TOTAL   7845600

// Scratch. All control state returns to zero by replay end -> replay-invariant.
__device__ float g_align[BSNMNA];
__device__ float g_overlaps[BSNMNA];
__device__ float g_cent[BSNMNA];
__device__ __align__(16) float g_dist[(size_t)BSNMNA * NBINS];
__device__ int   g_liveA[NBM * MAXL];
__device__ int   g_cnt[NBM];
__device__ unsigned g_inbits[BSNA];     // sparse atomicOr; re-zeroed by k_assign
__device__ unsigned g_topkbits[BSNA];
__device__ unsigned g_posA[NBM];
__device__ unsigned g_posO[NBM];
__device__ int g_blkdone[NBM];
__device__ unsigned g_bar1, g_bar2;

__device__ __forceinline__ unsigned long long ullmax2(unsigned long long a, unsigned long long b){ return a>b?a:b; }

__device__ __forceinline__ void ins4(unsigned long long key,
    unsigned long long& k0, unsigned long long& k1,
    unsigned long long& k2, unsigned long long& k3)
{
    if (key < k3) {
        k3 = key;
        unsigned long long tmp;
        if (k3 < k2) { tmp=k2; k2=k3; k3=tmp; }
        if (k2 < k1) { tmp=k1; k1=k2; k2=tmp; }
        if (k1 < k0) { tmp=k0; k0=k1; k1=tmp; }
    }
}

// ---------------------------------------------------------------------------
// K1: one thread per (bm, anchor); single ballot round; sparse inbits
// ---------------------------------------------------------------------------
__global__ __launch_bounds__(256) void k_compact(
    const float* __restrict__ anc,
    const float* __restrict__ gt_bboxes,
    const float* __restrict__ mask_gt)
{
    int t = blockIdx.x * blockDim.x + threadIdx.x;
    if (t < NBM) { g_posA[t] = 0u; g_posO[t] = 0u; }
    if (t >= NBM * NAP) return;

    int bm = t / NAP;
    int a  = t - bm * NAP;
    int lane = threadIdx.x & 31;

    bool live = false;
    if (a < NA && __ldg(&mask_gt[bm]) != 0.f) {
        float2 p = __ldg(&((const float2*)anc)[a]);
        float lx = __ldg(&gt_bboxes[bm*4+0]);
        float ly = __ldg(&gt_bboxes[bm*4+1]);
        float rx = __ldg(&gt_bboxes[bm*4+2]);
        float ry = __ldg(&gt_bboxes[bm*4+3]);
        float mind = fminf(fminf(p.x - lx, p.y - ly), fminf(rx - p.x, ry - p.y));
        live = (mind > 1e-9f);
    }
    unsigned set = __ballot_sync(FULLM, live);   // whole warp shares one bm
    if (set) {
        int leader = __ffs(set) - 1;
        int base = 0;
        if (lane == leader) base = atomicAdd(&g_cnt[bm], __popc(set));
        base = __shfl_sync(FULLM, base, leader);
        if (live) {
            int s = base + __popc(set & ((1u << lane) - 1u));
            if (s < MAXL) g_liveA[bm*MAXL + s] = a;
            int b = bm / NM, m = bm - b*NM;
            atomicOr(&g_inbits[b*NA + a], 1u << m);
        }
    }
}

// ---------------------------------------------------------------------------
// K2: warp-per-pair heavy work + last-block-per-bm fused top-13
// ---------------------------------------------------------------------------
struct WarpScratch {
    unsigned long long sAI[NPT];  // (ang_bits<<32)|idx, bucket-contiguous CSR
    float r2[NPT];                // squared distance, indexed by point id
    int scnt[NB2];
    int scur[NB2];
    int pfx2[3*NB2 + 1];          // tripled exclusive prefix (no mod in ring math)
};

union SmemPool {
    WarpScratch ws[WPB];
    unsigned long long s_topk[MAXL];   // used only after block-wide syncthreads
};

__global__ __launch_bounds__(32*WPB) void k_pairs(
    const float* __restrict__ pd_scores,
    const float* __restrict__ pd_bboxes,
    const float* __restrict__ anc,
    const int*   __restrict__ gt_labels,
    const float* __restrict__ gt_coor)
{
    __shared__ SmemPool sp;
    __shared__ int sLast;

    int bm = blockIdx.y;
    int cnt = g_cnt[bm];
    if (cnt > MAXL) cnt = MAXL;
    if ((int)blockIdx.x * WPB >= cnt) return;   // whole block idle
    int nPart = (cnt + WPB - 1) / WPB;

    int wid = threadIdx.x >> 5;
    int lane = threadIdx.x & 31;
    int j = blockIdx.x * WPB + wid;
    int b = bm / NM;

    if (j < cnt) {
        WarpScratch& S = sp.ws[wid];
        const float2* gp2 = (const float2*)(gt_coor + (size_t)bm * (2*NPT));
        int label = gt_labels[bm];

        int a = g_liveA[bm*MAXL + j];
        float2 ap = ((const float2*)anc)[a];
        float ax = ap.x, ay = ap.y;
        int pairIdx = bm * NA + a;

        // zero 72 bucket counts
        S.scnt[lane] = 0;
        S.scnt[32 + lane] = 0;
        if (lane < 8) S.scnt[64 + lane] = 0;
        __syncwarp();

        // point phase: r2 + angle + bucket count (angles stay in registers)
        float angR[12];
        #pragma unroll
        for (int i = 0; i < 12; i++) {
            int p = lane + 32*i;
            if (p < NPT) {
                float2 pt = gp2[p];
                float dx = pt.x - ax, dy = pt.y - ay;
                S.r2[p] = dx*dx + dy*dy;
                float ang = atan2f(dy, dx) * 57.29577951308232f;
                if (ang < 0.f) ang += 360.f;
                angR[i] = ang;
                int bk = (int)(ang * 0.2f);
                if (bk > NB2-1) bk = NB2-1;
                atomicAdd(&S.scnt[bk], 1);
            }
        }
        __syncwarp();

        // exclusive scan over 72 counts -> tripled prefix pfx2 + cursors
        {
            int v0 = S.scnt[lane];
            int v1 = S.scnt[32 + lane];
            int v2 = (lane < 8) ? S.scnt[64 + lane] : 0;
            int c0 = v0, c1 = v1, c2 = v2;
            #pragma unroll
            for (int off = 1; off < 32; off <<= 1) {
                int n0 = __shfl_up_sync(FULLM, c0, off);
                int n1 = __shfl_up_sync(FULLM, c1, off);
                if (lane >= off) { c0 += n0; c1 += n1; }
            }
            int tot0 = __shfl_sync(FULLM, c0, 31);
            int tot01 = tot0 + __shfl_sync(FULLM, c1, 31);
            #pragma unroll
            for (int off = 1; off < 8; off <<= 1) {
                int n2 = __shfl_up_sync(FULLM, c2, off);
                if (lane >= off) c2 += n2;
            }
            int e0 = c0 - v0;
            int e1 = tot0 + c1 - v1;
            int e2 = tot01 + c2 - v2;
            S.scur[lane] = e0;
            S.pfx2[lane] = e0; S.pfx2[lane+NB2] = e0+NPT; S.pfx2[lane+2*NB2] = e0+2*NPT;
            int k1i = 32 + lane;
            S.scur[k1i] = e1;
            S.pfx2[k1i] = e1; S.pfx2[k1i+NB2] = e1+NPT; S.pfx2[k1i+2*NB2] = e1+2*NPT;
            if (lane < 8) {
                int k2i = 64 + lane;
                S.scur[k2i] = e2;
                S.pfx2[k2i] = e2; S.pfx2[k2i+NB2] = e2+NPT; S.pfx2[k2i+2*NB2] = e2+2*NPT;
            }
            if (lane == 0) S.pfx2[3*NB2] = 3*NPT;
        }
        __syncwarp();

        // scatter: packed (ang,idx) bucket-contiguous (bucket recomputed)
        #pragma unroll
        for (int i = 0; i < 12; i++) {
            int p = lane + 32*i;
            if (p < NPT) {
                int bk = (int)(angR[i] * 0.2f);
                if (bk > NB2-1) bk = NB2-1;
                int pos = atomicAdd(&S.scur[bk], 1);
                S.sAI[pos] = ((unsigned long long)__float_as_uint(angR[i]) << 32) | (unsigned)p;
            }
        }
        __syncwarp();

        // bin phase: lane-owned bins, minimal count>=4 ring at 5-deg buckets
        float dmv0 = 1e-6f, dmv1 = 1e-6f;
        #pragma unroll
        for (int pass = 0; pass < 2; pass++) {
            int bin = lane + 32*pass;
            if (pass == 1 && lane >= 4) break;
            int i0 = 2*bin;
            float dmv;
            int c0cnt = S.pfx2[i0+73] - S.pfx2[i0+71];   // buckets 2bin-1,2bin: diff < 5
            if (c0cnt == 0) {
                dmv = 1e-6f;            // nearest candidate diff >= 5 > 3
            } else {
                int L = 0, lo, hi;
                for (;; L++) {
                    lo = S.pfx2[i0+71-L];
                    hi = S.pfx2[i0+73+L];
                    if (hi - lo >= 4) break;
                }
                int W, pos, n1;
                if (2*L + 2 >= NB2) { pos = 0; W = NPT; n1 = NPT; }
                else {
                    W = hi - lo;
                    pos = lo; while (pos >= NPT) pos -= NPT;
                    n1 = NPT - pos; if (n1 > W) n1 = W;
                }

                float th = (float)(bin * 10);
                unsigned long long k0=~0ull,k1=~0ull,k2=~0ull,k3=~0ull;
                for (int c = 0; c < n1; c++) {
                    unsigned long long ai = S.sAI[pos + c];
                    float ang = __uint_as_float((unsigned)(ai >> 32));
                    float df = fabsf(ang - th);
                    if (df > 180.f) df = 360.f - df;
                    ins4(((unsigned long long)__float_as_uint(df) << 32) |
                         (unsigned)(ai & 0xffffffffu), k0, k1, k2, k3);
                }
                for (int c = 0; c < W - n1; c++) {
                    unsigned long long ai = S.sAI[c];
                    float ang = __uint_as_float((unsigned)(ai >> 32));
                    float df = fabsf(ang - th);
                    if (df > 180.f) df = 360.f - df;
                    ins4(((unsigned long long)__float_as_uint(df) << 32) |
                         (unsigned)(ai & 0xffffffffu), k0, k1, k2, k3);
                }
                float mindiff = __uint_as_float((unsigned)(k0 >> 32));
                if (mindiff > 3.0f) {
                    dmv = 1e-6f;
                } else {
                    float mr2 = S.r2[(unsigned)(k0 & 0xffffffffu)];
                    mr2 = fmaxf(mr2, S.r2[(unsigned)(k1 & 0xffffffffu)]);
                    mr2 = fmaxf(mr2, S.r2[(unsigned)(k2 & 0xffffffffu)]);
                    mr2 = fmaxf(mr2, S.r2[(unsigned)(k3 & 0xffffffffu)]);
                    dmv = fmaxf(sqrtf(mr2), 1e-6f);   // sqrt∘max == max∘sqrt
                }
            }
            if (pass == 0) dmv0 = dmv; else dmv1 = dmv;
        }

        // g_dist write (lane-owned bins)
        {
            float* gd = g_dist + (size_t)pairIdx * NBINS;
            gd[lane] = dmv0;
            if (lane < 4) gd[32 + lane] = dmv1;
        }

        // epilogue: iou + centerness + align (lane-owned dm values; R12-proven)
        {
            const float* pb = pd_bboxes + ((size_t)b*NA + a) * NBINS;
            float p0v = pb[lane];
            float smin = fmaxf(fminf(dmv0, p0v), 1e-6f);
            float smax = fmaxf(dmv0, p0v);
            float mn = dmv0, mx = dmv0;
            if (lane < 4) {
                float p1v = pb[32 + lane];
                smin += fmaxf(fminf(dmv1, p1v), 1e-6f);
                smax += fmaxf(dmv1, p1v);
                mn = fminf(mn, dmv1);
                mx = fmaxf(mx, dmv1);
            }
            #pragma unroll
            for (int off = 16; off; off >>= 1) {
                smin += __shfl_xor_sync(FULLM, smin, off);
                smax += __shfl_xor_sync(FULLM, smax, off);
                mn = fminf(mn, __shfl_xor_sync(FULLM, mn, off));
                mx = fmaxf(mx, __shfl_xor_sync(FULLM, mx, off));
            }
            if (lane == 0) {
                float iou = smin / smax;
                float score = pd_scores[((size_t)b*NA + a) * NC + label];
                g_overlaps[pairIdx] = iou;
                g_align[pairIdx]    = score * iou * iou * iou;
                g_cent[pairIdx]     = sqrtf(mn / mx);
            }
        }
    }

    // ---- fused top-13: last finishing block of this bm runs the warp topk ----
    __syncthreads();            // retires all ws usage before s_topk reuse
    if (threadIdx.x == 0) {
        __threadfence();                              // release g_align writes
        int old = atomicAdd(&g_blkdone[bm], 1);
        sLast = (old == nPart - 1) ? 1 : 0;
        if (sLast) g_blkdone[bm] = 0;                 // all arrived; reset for replay
    }
    __syncthreads();
    if (sLast && threadIdx.x < 32) {
        __threadfence();                              // acquire other blocks' writes
        const int* la = g_liveA + bm*MAXL;
        for (int jj = lane; jj < cnt; jj += 32) {
            int a = la[jj];
            float v = g_align[bm*NA + a];
            sp.s_topk[jj] = ((unsigned long long)__float_as_uint(v) << 32) | (unsigned)(NA - a);
        }
        __syncwarp();
        int m = bm % NM;
        int kmax = cnt < 13 ? cnt : 13;
        for (int k = 0; k < kmax; k++) {
            unsigned long long best = 0;
            for (int jj = lane; jj < cnt; jj += 32) best = ullmax2(best, sp.s_topk[jj]);
            #pragma unroll
            for (int off = 16; off; off >>= 1)
                best = ullmax2(best, __shfl_xor_sync(FULLM, best, off));
            if (best == 0) break;   // padding picks carry mask_pos=0 in reference
            for (int jj = lane; jj < cnt; jj += 32) if (sp.s_topk[jj] == best) sp.s_topk[jj] = 0;
            if (lane == 0) {
                int a = NA - (int)(best & 0xffffffffu);
                atomicOr(&g_topkbits[b*NA + a], 1u << m);
            }
            __syncwarp();
        }
    }
}

// ---------------------------------------------------------------------------
// K3: fused per-anchor resolution + outputs + grid barrier + target_scores
// ---------------------------------------------------------------------------
__global__ __launch_bounds__(256) void k_assign(
    const int*   __restrict__ gt_labels,
    const float* __restrict__ gt_bboxes,
    float* __restrict__ out)
{
    int t = blockIdx.x * blockDim.x + threadIdx.x;
    bool valid = t < BSNA;
    unsigned fin = 0;
    int b = 0, a = 0;

    if (valid) {
        b = t / NA; a = t % NA;
        unsigned tb  = g_topkbits[t];
        unsigned inb = g_inbits[t];
        g_topkbits[t] = 0u;               // reset for next replay
        g_inbits[t]   = 0u;               // reset (compact ORs sparsely)
        fin = tb;
        if (__popc(tb) > 1) {
            float best = -1.f; int bi = 0;
            #pragma unroll
            for (int m = 0; m < NM; m++) {
                float o = ((inb >> m) & 1u) ? g_overlaps[(b*NM+m)*NA + a] : 0.f;
                if (o > best) { best = o; bi = m; }   // first max kept
            }
            fin = 1u << bi;
        }

        int tgt = fin ? (__ffs(fin) - 1) : 0;
        out[FG_OFF + t]  = fin ? 1.f : 0.f;
        out[TGI_OFF + t] = (float)tgt;
        int lbl = gt_labels[b*NM + tgt]; if (lbl < 0) lbl = 0;
        out[TL_OFF + t] = (float)lbl;
        const float4* gb4 = (const float4*)(gt_bboxes);
        ((float4*)(out + TB_OFF))[t] = gb4[b*NM + tgt];

        if (fin) {
            int idx = (b*NM + tgt)*NA + a;
            out[MPB_OFF + idx]  = 1.f;
            out[CENT_OFF + idx] = g_cent[idx];
            atomicMax(&g_posA[b*NM + tgt], __float_as_uint(g_align[idx]));
            atomicMax(&g_posO[b*NM + tgt], __float_as_uint(g_overlaps[idx]));
            const float4* src = (const float4*)(g_dist + (size_t)idx * NBINS);
            float4* dst = (float4*)(out + GTDIST_OFF + (size_t)idx * NBINS);
            #pragma unroll
            for (int e = 0; e < NBINS/4; e++) dst[e] = src[e];
        }
    }
    if (t < NBM) g_cnt[t] = 0;            // reset for next replay (k_pairs done)

    // ---- software grid barrier (two counters; all ABLK blocks co-resident) ----
    if (threadIdx.x == 0) {
        __threadfence();
        atomicAdd(&g_bar1, 1u);
        while (*((volatile unsigned*)&g_bar1) < ABLK) { }
        __threadfence();
        unsigned o2 = atomicAdd(&g_bar2, 1u);
        if (o2 == ABLK - 1) {             // everyone passed the spin
            atomicExch(&g_bar1, 0u);
            atomicExch(&g_bar2, 0u);
        }
    }
    __syncthreads();

    // ---- phase 2: target_scores for positives ----
    if (valid && fin) {
        int m = __ffs(fin) - 1;
        int bm = b*NM + m;
        float A = __uint_as_float(g_posA[bm]);
        float O = __uint_as_float(g_posO[bm]);
        float norm = g_align[bm*NA + a] * O / (A + 1e-9f);
        int lbl = gt_labels[bm]; if (lbl < 0) lbl = 0;
        out[TS_OFF + (size_t)t * NC + lbl] = norm;
    }
}

// ---------------------------------------------------------------------------
// Stream order: memset -> compact -> pairs -> assign.
// (memset first: dependency-free, absorbs graph cold-start in a driver op.)
// ---------------------------------------------------------------------------
extern "C" void kernel_launch(void* const* d_in, const int* in_sizes, int n_in,
                              void* d_out, int out_size) {
    const float* pd_scores = (const float*)d_in[0];
    const float* pd_bboxes = (const float*)d_in[1];
    const float* anc       = (const float*)d_in[2];
    const int*   gt_labels = (const int*)  d_in[3];
    const float* gt_bboxes = (const float*)d_in[4];
    const float* mask_gt   = (const float*)d_in[5];
    const float* gt_coor   = (const float*)d_in[6];
    float* out = (float*)d_out;

    cudaMemsetAsync(out, 0, (size_t)OUT_TOTAL * sizeof(float));
    k_compact<<<(NBM*NAP + 255)/256, 256>>>(anc, gt_bboxes, mask_gt);
    dim3 g1((MAXL + WPB - 1)/WPB, NBM);
    k_pairs<<<g1, 32*WPB>>>(pd_scores, pd_bboxes, anc, gt_labels, gt_coor);
    k_assign<<<ABLK, 256>>>(gt_labels, gt_bboxes, out);
}